// round 1
// baseline (speedup 1.0000x reference)
#include <cuda_runtime.h>
#include <cuda_bf16.h>
#include <math.h>

// ---------------- problem constants ----------------
#define B        4096
#define FEAT_K   4096     // 2*1024 + 8*256
#define NCH      256      // received channels
#define XSAMP    (3*64*64)

// ---------------- scratch (device globals; no allocs allowed) ----------------
__device__ float g_feat[(size_t)B * FEAT_K];   // 64 MiB
__device__ float g_WT[(size_t)FEAT_K * NCH];   // 4 MiB, layout [k][j]
__device__ float g_recv[(size_t)B * NCH];      // 4 MiB
__device__ float g_s[10 * 256];
__device__ float g_noise[256];
__device__ float g_cwf[10 * 4 * 27];           // BN-folded conv weights
__device__ float g_cbf[10 * 4];                // BN-folded conv bias

// =================================================================
// prep_s: grid(10) x 256 threads. s[n,j] = b_mat[n,j]*h_vec[n,j],
// noise_term[j], BN-folded conv weights.
// =================================================================
__global__ void prep_s_kernel(const float* __restrict__ b_mat,
                              const float* __restrict__ h_mat,
                              const float* __restrict__ a_mat,
                              const float* __restrict__ indicator,
                              const float* __restrict__ noise,
                              const float* __restrict__ conv_w,
                              const float* __restrict__ conv_b,
                              const float* __restrict__ gamma,
                              const float* __restrict__ beta,
                              const float* __restrict__ mean,
                              const float* __restrict__ var)
{
    int n = blockIdx.x;
    int j = threadIdx.x;   // 0..255

    // arow[j][c] = sum_m a_mat[j,c,m]
    float arow[5];
#pragma unroll
    for (int c = 0; c < 5; c++) {
        float s = 0.f;
#pragma unroll
        for (int m = 0; m < 5; m++) s += a_mat[(j * 5 + c) * 5 + m];
        arow[c] = s;
    }

    // h_sel[n,j,c] = sum_k indicator[j,k] * h_mat[n,k,c]
    float hs[5] = {0.f, 0.f, 0.f, 0.f, 0.f};
    for (int k = 0; k < 64; k++) {
        float iv = indicator[j * 64 + k];
#pragma unroll
        for (int c = 0; c < 5; c++) hs[c] += iv * h_mat[(n * 64 + k) * 5 + c];
    }
    float hv = 0.f;
#pragma unroll
    for (int c = 0; c < 5; c++) hv += hs[c] * arow[c];

    g_s[n * 256 + j] = b_mat[n * 256 + j] * hv;

    if (n == 0) {
        float nt = 0.f;
#pragma unroll
        for (int c = 0; c < 5; c++) nt += noise[j * 5 + c] * arow[c];
        g_noise[j] = nt;
    }

    // fold BN into conv weights: block n handles its 4*27 weights
    if (j < 108) {
        int co = j / 27, r = j % 27;
        int idx = n * 4 + co;
        float sc = gamma[idx] * rsqrtf(var[idx] + 1e-5f);
        g_cwf[idx * 27 + r] = conv_w[idx * 27 + r] * sc;
        if (r == 0)
            g_cbf[idx] = (conv_b[idx] - mean[idx]) * sc + beta[idx];
    }
}

// =================================================================
// prep_w: grid(4096) x 256. g_WT[k][j] = cut_w[n][j][kk] * s[n][j]
// feature k layout: [branch0 1024][branch1 1024][branch2..9 256 each]
// =================================================================
__global__ void prep_w_kernel(const float* __restrict__ cut_big,
                              const float* __restrict__ cut_small)
{
    int k = blockIdx.x;
    int j = threadIdx.x;
    float cw; int n;
    if (k < 2048) {
        n = k >> 10;
        int kk = k & 1023;
        cw = cut_big[((size_t)(n * 256 + j)) * 1024 + kk];
    } else {
        int g = k - 2048;
        int n2 = g >> 8;
        int kk = g & 255;
        n = n2 + 2;
        cw = cut_small[((size_t)(n2 * 256 + j)) * 256 + kk];
    }
    g_WT[(size_t)k * 256 + j] = cw * g_s[n * 256 + j];
}

// =================================================================
// branch: grid(4096 samples) x 256 threads. One sample per block,
// whole x-sample in smem, each thread computes 16 consecutive
// pooled features (conv+BN+ReLU+2x2maxpool fused).
// dyn smem: 12288 (x) + 1080 (w) + 40 (b) floats = 53632 B
// =================================================================
__global__ void branch_kernel(const float* __restrict__ x)
{
    extern __shared__ float sm[];
    float* sx = sm;                 // [3][64][64]
    float* sw = sm + 12288;         // folded conv weights, 1080
    float* sb = sw + 1080;          // folded bias, 40

    int b = blockIdx.x;
    int tid = threadIdx.x;

    const float4* xin = (const float4*)(x + (size_t)b * XSAMP);
    float4* sx4 = (float4*)sx;
#pragma unroll 4
    for (int i = tid; i < XSAMP / 4; i += 256) sx4[i] = xin[i];
    for (int i = tid; i < 1080; i += 256) sw[i] = g_cwf[i];
    if (tid < 40) sb[tid] = g_cbf[tid];
    __syncthreads();

    float res[16];
#pragma unroll
    for (int q = 0; q < 16; q++) {
        int f = tid * 16 + q;
        int n, co, pi, pj, R0, C0, HW;
        if (f < 2048) {
            n = f >> 10;
            int w_ = f & 1023;
            co = w_ >> 8; pi = (w_ >> 4) & 15; pj = w_ & 15;
            R0 = 32 * n; C0 = 0; HW = 32;
        } else {
            int g = f - 2048;
            int n2 = g >> 8;
            n = n2 + 2;
            int w_ = g & 255;
            co = w_ >> 6; pi = (w_ >> 3) & 7; pj = w_ & 7;
            R0 = (16 * n2) & 63; C0 = 32 + 16 * (n2 >> 2); HW = 16;
        }
        const float* wp = sw + (n * 4 + co) * 27;
        float wreg[27];
#pragma unroll
        for (int t = 0; t < 27; t++) wreg[t] = wp[t];
        float bias = sb[n * 4 + co];

        float t00 = bias, t01 = bias, t10 = bias, t11 = bias;
        int ib = 2 * pi - 1, jb = 2 * pj - 1;
#pragma unroll
        for (int ci = 0; ci < 3; ci++) {
            float p[4][4];
#pragma unroll
            for (int u = 0; u < 4; u++) {
                int a = ib + u;
                bool va = (a >= 0) && (a < HW);
#pragma unroll
                for (int v = 0; v < 4; v++) {
                    int c2 = jb + v;
                    bool vc = (c2 >= 0) && (c2 < HW);
                    p[u][v] = (va && vc) ? sx[ci * 4096 + (R0 + a) * 64 + (C0 + c2)] : 0.f;
                }
            }
#pragma unroll
            for (int di = 0; di < 3; di++)
#pragma unroll
                for (int dj = 0; dj < 3; dj++) {
                    float wv = wreg[ci * 9 + di * 3 + dj];
                    t00 += p[di    ][dj    ] * wv;
                    t01 += p[di    ][dj + 1] * wv;
                    t10 += p[di + 1][dj    ] * wv;
                    t11 += p[di + 1][dj + 1] * wv;
                }
        }
        float mx = fmaxf(fmaxf(t00, t01), fmaxf(t10, t11));
        res[q] = fmaxf(mx, 0.f);
    }
    float4* outp = (float4*)(g_feat + (size_t)b * FEAT_K + tid * 16);
#pragma unroll
    for (int u = 0; u < 4; u++)
        outp[u] = make_float4(res[4 * u], res[4 * u + 1], res[4 * u + 2], res[4 * u + 3]);
}

// =================================================================
// gemm: recv[b][j] = feat[b][:] . WT[:][j] + noise[j]
// BM=128 BN=64 BK=16, 256 threads, 8x4 per-thread tile.
// grid (4096/128, 256/64) = (32, 4)
// =================================================================
#define GBM 128
#define GBN 64
#define GBK 16
#define APITCH 136

__global__ void gemm_kernel()
{
    __shared__ float As[GBK * APITCH];
    __shared__ float Bs[GBK * GBN];

    int tid = threadIdx.x;
    int m0 = blockIdx.x * GBM;
    int n0 = blockIdx.y * GBN;
    int tx = tid & 15;     // N dir, 4 cols each
    int ty = tid >> 4;     // M dir, 8 rows each

    float acc[8][4];
#pragma unroll
    for (int i = 0; i < 8; i++)
#pragma unroll
        for (int j = 0; j < 4; j++) acc[i][j] = 0.f;

    for (int k0 = 0; k0 < FEAT_K; k0 += GBK) {
        // A tile 128x16, transposed into As[k][m]
#pragma unroll
        for (int r = 0; r < 2; r++) {
            int v = tid + 256 * r;
            int row = v >> 2, kq = v & 3;
            float4 a4 = *(const float4*)(g_feat + (size_t)(m0 + row) * FEAT_K + k0 + kq * 4);
            As[(kq * 4 + 0) * APITCH + row] = a4.x;
            As[(kq * 4 + 1) * APITCH + row] = a4.y;
            As[(kq * 4 + 2) * APITCH + row] = a4.z;
            As[(kq * 4 + 3) * APITCH + row] = a4.w;
        }
        // B tile 16x64
        {
            int kk = tid >> 4, jv = tid & 15;
            float4 b4 = *(const float4*)(g_WT + (size_t)(k0 + kk) * NCH + n0 + jv * 4);
            *(float4*)(Bs + kk * GBN + jv * 4) = b4;
        }
        __syncthreads();
#pragma unroll
        for (int kk = 0; kk < GBK; kk++) {
            float a[8], bb[4];
            float4 a0 = *(float4*)(As + kk * APITCH + ty * 8);
            float4 a1 = *(float4*)(As + kk * APITCH + ty * 8 + 4);
            a[0] = a0.x; a[1] = a0.y; a[2] = a0.z; a[3] = a0.w;
            a[4] = a1.x; a[5] = a1.y; a[6] = a1.z; a[7] = a1.w;
            float4 b0 = *(float4*)(Bs + kk * GBN + tx * 4);
            bb[0] = b0.x; bb[1] = b0.y; bb[2] = b0.z; bb[3] = b0.w;
#pragma unroll
            for (int i = 0; i < 8; i++)
#pragma unroll
                for (int j = 0; j < 4; j++) acc[i][j] += a[i] * bb[j];
        }
        __syncthreads();
    }

    float4 nz = *(const float4*)(g_noise + n0 + tx * 4);
#pragma unroll
    for (int i = 0; i < 8; i++) {
        int row = m0 + ty * 8 + i;
        float4 o = make_float4(acc[i][0] + nz.x, acc[i][1] + nz.y,
                               acc[i][2] + nz.z, acc[i][3] + nz.w);
        *(float4*)(g_recv + (size_t)row * NCH + n0 + tx * 4) = o;
    }
}

// =================================================================
// mlp: warp-per-sample. weights in smem with conflict-free pitch.
// grid(128) x 256 threads (8 warps), 4 samples per warp.
// dyn smem = 45590 floats = 182360 B
// =================================================================
#define W1P 257
#define W2P 129
#define W3P 65

__global__ void mlp_kernel(const float* __restrict__ fc1w, const float* __restrict__ fc1b,
                           const float* __restrict__ fc2w, const float* __restrict__ fc2b,
                           const float* __restrict__ outw, const float* __restrict__ outb,
                           float* __restrict__ out)
{
    extern __shared__ float sm[];
    float* W1 = sm;                     // 128 x 257
    float* W2 = W1 + 128 * W1P;         // 64 x 129
    float* W3 = W2 + 64 * W2P;          // 10 x 65
    float* B1 = W3 + 10 * W3P;          // 128
    float* B2 = B1 + 128;               // 64
    float* B3 = B2 + 64;                // 12
    float* scratch = B3 + 12;           // 8 warps * 448

    int tid = threadIdx.x;
    for (int t = tid; t < 128 * 256; t += 256) {
        int o = t >> 8, j = t & 255;
        W1[o * W1P + j] = fc1w[t];
    }
    for (int t = tid; t < 64 * 128; t += 256) {
        int o = t >> 7, j = t & 127;
        W2[o * W2P + j] = fc2w[t];
    }
    for (int t = tid; t < 640; t += 256) {
        int o = t >> 6, j = t & 63;
        W3[o * W3P + j] = outw[t];
    }
    if (tid < 128) B1[tid] = fc1b[tid];
    if (tid < 64)  B2[tid] = fc2b[tid];
    if (tid < 10)  B3[tid] = outb[tid];
    __syncthreads();

    int warp = tid >> 5, lane = tid & 31;
    float* rv = scratch + warp * 448;
    float* h2 = rv + 256;
    float* h3 = h2 + 128;

    for (int q = 0; q < 4; q++) {
        int s = (blockIdx.x * 8 + warp) * 4 + q;
        // h1 = relu(received)
#pragma unroll
        for (int u = 0; u < 8; u++)
            rv[lane + u * 32] = fmaxf(g_recv[(size_t)s * NCH + lane + u * 32], 0.f);
        __syncwarp();
        // fc1 + relu
#pragma unroll
        for (int u = 0; u < 4; u++) {
            int o = lane + u * 32;
            float acc = B1[o];
#pragma unroll 8
            for (int j = 0; j < 256; j++) acc += rv[j] * W1[o * W1P + j];
            h2[o] = fmaxf(acc, 0.f);
        }
        __syncwarp();
        // fc2 + relu
#pragma unroll
        for (int u = 0; u < 2; u++) {
            int o = lane + u * 32;
            float acc = B2[o];
#pragma unroll 8
            for (int j = 0; j < 128; j++) acc += h2[j] * W2[o * W2P + j];
            h3[o] = fmaxf(acc, 0.f);
        }
        __syncwarp();
        // out + log_softmax
        float logit = -INFINITY;
        if (lane < 10) {
            float acc = B3[lane];
#pragma unroll 8
            for (int j = 0; j < 64; j++) acc += h3[j] * W3[lane * W3P + j];
            logit = acc;
        }
        float m = logit;
#pragma unroll
        for (int off = 16; off; off >>= 1) m = fmaxf(m, __shfl_xor_sync(0xFFFFFFFFu, m, off));
        float e = (lane < 10) ? expf(logit - m) : 0.f;
        float ssum = e;
#pragma unroll
        for (int off = 16; off; off >>= 1) ssum += __shfl_xor_sync(0xFFFFFFFFu, ssum, off);
        if (lane < 10) out[s * 10 + lane] = logit - m - logf(ssum);
    }
}

// =================================================================
// launch
// =================================================================
extern "C" void kernel_launch(void* const* d_in, const int* in_sizes, int n_in,
                              void* d_out, int out_size)
{
    const float* x        = (const float*)d_in[0];
    const float* conv_w   = (const float*)d_in[1];
    const float* conv_b   = (const float*)d_in[2];
    const float* bn_gamma = (const float*)d_in[3];
    const float* bn_beta  = (const float*)d_in[4];
    const float* bn_mean  = (const float*)d_in[5];
    const float* bn_var   = (const float*)d_in[6];
    const float* cut_big  = (const float*)d_in[7];
    const float* cut_small= (const float*)d_in[8];
    const float* fc1_w    = (const float*)d_in[9];
    const float* fc1_b    = (const float*)d_in[10];
    const float* fc2_w    = (const float*)d_in[11];
    const float* fc2_b    = (const float*)d_in[12];
    const float* out_w    = (const float*)d_in[13];
    const float* out_b    = (const float*)d_in[14];
    const float* b_mat    = (const float*)d_in[15];
    const float* h_mat    = (const float*)d_in[16];
    const float* a_mat    = (const float*)d_in[17];
    const float* indicator= (const float*)d_in[18];
    const float* noise    = (const float*)d_in[19];
    float* out = (float*)d_out;

    static int attr_done = 0;
    cudaFuncSetAttribute(branch_kernel, cudaFuncAttributeMaxDynamicSharedMemorySize, 56 * 1024);
    cudaFuncSetAttribute(mlp_kernel, cudaFuncAttributeMaxDynamicSharedMemorySize, 186 * 1024);
    (void)attr_done;

    prep_s_kernel<<<10, 256>>>(b_mat, h_mat, a_mat, indicator, noise,
                               conv_w, conv_b, bn_gamma, bn_beta, bn_mean, bn_var);
    prep_w_kernel<<<4096, 256>>>(cut_big, cut_small);
    branch_kernel<<<4096, 256, 56 * 1024>>>(x);
    gemm_kernel<<<dim3(32, 4), 256>>>();
    mlp_kernel<<<128, 256, 186 * 1024>>>(fc1_w, fc1_b, fc2_w, fc2_b, out_w, out_b, out);
}

// round 2
// speedup vs baseline: 1.2376x; 1.2376x over previous
#include <cuda_runtime.h>
#include <cuda_bf16.h>
#include <math.h>
#include <stdint.h>

// ---------------- problem constants ----------------
#define B        4096
#define FEAT_K   4096     // 2*1024 + 8*256
#define NCH      256      // received channels
#define XSAMP    (3*64*64)

// ---------------- scratch (device globals; no allocs allowed) ----------------
__device__ __nv_bfloat16 g_featH[(size_t)B * FEAT_K];   // 32 MiB
__device__ __nv_bfloat16 g_featL[(size_t)B * FEAT_K];   // 32 MiB
__device__ __nv_bfloat16 g_WTH[(size_t)NCH * FEAT_K];   // 2 MiB, layout [j][k]
__device__ __nv_bfloat16 g_WTL[(size_t)NCH * FEAT_K];   // 2 MiB
__device__ float g_recv[(size_t)B * NCH];               // 4 MiB
__device__ float g_s[10 * 256];
__device__ float g_noise[256];
__device__ float g_cwf[10 * 4 * 27];                    // BN-folded conv weights
__device__ float g_cbf[10 * 4];                         // BN-folded conv bias

// =================================================================
// prep_s: grid(10) x 256 threads. s[n,j] = b_mat[n,j]*h_vec[n,j],
// noise_term[j], BN-folded conv weights.
// =================================================================
__global__ void prep_s_kernel(const float* __restrict__ b_mat,
                              const float* __restrict__ h_mat,
                              const float* __restrict__ a_mat,
                              const float* __restrict__ indicator,
                              const float* __restrict__ noise,
                              const float* __restrict__ conv_w,
                              const float* __restrict__ conv_b,
                              const float* __restrict__ gamma,
                              const float* __restrict__ beta,
                              const float* __restrict__ mean,
                              const float* __restrict__ var)
{
    int n = blockIdx.x;
    int j = threadIdx.x;   // 0..255

    float arow[5];
#pragma unroll
    for (int c = 0; c < 5; c++) {
        float s = 0.f;
#pragma unroll
        for (int m = 0; m < 5; m++) s += a_mat[(j * 5 + c) * 5 + m];
        arow[c] = s;
    }

    float hs[5] = {0.f, 0.f, 0.f, 0.f, 0.f};
    for (int k = 0; k < 64; k++) {
        float iv = indicator[j * 64 + k];
#pragma unroll
        for (int c = 0; c < 5; c++) hs[c] += iv * h_mat[(n * 64 + k) * 5 + c];
    }
    float hv = 0.f;
#pragma unroll
    for (int c = 0; c < 5; c++) hv += hs[c] * arow[c];

    g_s[n * 256 + j] = b_mat[n * 256 + j] * hv;

    if (n == 0) {
        float nt = 0.f;
#pragma unroll
        for (int c = 0; c < 5; c++) nt += noise[j * 5 + c] * arow[c];
        g_noise[j] = nt;
    }

    if (j < 108) {
        int co = j / 27, r = j % 27;
        int idx = n * 4 + co;
        float sc = gamma[idx] * rsqrtf(var[idx] + 1e-5f);
        g_cwf[idx * 27 + r] = conv_w[idx * 27 + r] * sc;
        if (r == 0)
            g_cbf[idx] = (conv_b[idx] - mean[idx]) * sc + beta[idx];
    }
}

// =================================================================
// prep_w: grid(2560) x 256. W_fold row-major [j][k], bf16 hi/lo.
// block = n*256 + j. Coalesced reads and writes.
// =================================================================
__global__ void prep_w_kernel(const float* __restrict__ cut_big,
                              const float* __restrict__ cut_small)
{
    int blk = blockIdx.x;
    int n = blk >> 8, j = blk & 255;
    float s = g_s[n * 256 + j];
    int tid = threadIdx.x;

    if (n < 2) {
        const float* src = cut_big + ((size_t)(n * 256 + j)) * 1024;
        size_t dst = (size_t)j * FEAT_K + n * 1024;
#pragma unroll
        for (int kk = tid; kk < 1024; kk += 256) {
            float v = src[kk] * s;
            __nv_bfloat16 h = __float2bfloat16(v);
            g_WTH[dst + kk] = h;
            g_WTL[dst + kk] = __float2bfloat16(v - __bfloat162float(h));
        }
    } else {
        int n2 = n - 2;
        const float* src = cut_small + ((size_t)(n2 * 256 + j)) * 256;
        size_t dst = (size_t)j * FEAT_K + 2048 + n2 * 256;
        float v = src[tid] * s;
        __nv_bfloat16 h = __float2bfloat16(v);
        g_WTH[dst + tid] = h;
        g_WTL[dst + tid] = __float2bfloat16(v - __bfloat162float(h));
    }
}

// =================================================================
// branch: grid(4096 samples) x 256 threads. One sample per block.
// All 16 features of a thread share (n, co) -> hoist weights/bias.
// Output written as bf16 hi/lo.
// =================================================================
__device__ __forceinline__ float pool_feat(const float* __restrict__ sx,
                                           int R0, int C0, int HW,
                                           const float wreg[27], float bias,
                                           int pi, int pj)
{
    float t00 = bias, t01 = bias, t10 = bias, t11 = bias;
    int ib = 2 * pi - 1, jb = 2 * pj - 1;
    bool left = (jb >= 0);
    bool right = (jb + 3 < HW);
#pragma unroll
    for (int ci = 0; ci < 3; ci++) {
        const float* base = sx + ci * 4096 + R0 * 64 + C0;
        float p[4][4];
#pragma unroll
        for (int u = 0; u < 4; u++) {
            int a = ib + u;
            bool va = (a >= 0) && (a < HW);
            const float* rp = base + a * 64 + jb;
            p[u][0] = (va && left)  ? rp[0] : 0.f;
            p[u][1] = va            ? rp[1] : 0.f;
            p[u][2] = va            ? rp[2] : 0.f;
            p[u][3] = (va && right) ? rp[3] : 0.f;
        }
#pragma unroll
        for (int di = 0; di < 3; di++)
#pragma unroll
            for (int dj = 0; dj < 3; dj++) {
                float wv = wreg[ci * 9 + di * 3 + dj];
                t00 += p[di    ][dj    ] * wv;
                t01 += p[di    ][dj + 1] * wv;
                t10 += p[di + 1][dj    ] * wv;
                t11 += p[di + 1][dj + 1] * wv;
            }
    }
    float mx = fmaxf(fmaxf(t00, t01), fmaxf(t10, t11));
    return fmaxf(mx, 0.f);
}

__global__ void __launch_bounds__(256) branch_kernel(const float* __restrict__ x)
{
    extern __shared__ float sm[];
    float* sx = sm;                 // [3][64][64]
    float* sw = sm + 12288;         // folded conv weights, 1080
    float* sb = sw + 1080;          // folded bias, 40

    int b = blockIdx.x;
    int tid = threadIdx.x;

    const float4* xin = (const float4*)(x + (size_t)b * XSAMP);
    float4* sx4 = (float4*)sx;
#pragma unroll 4
    for (int i = tid; i < XSAMP / 4; i += 256) sx4[i] = xin[i];
    for (int i = tid; i < 1080; i += 256) sw[i] = g_cwf[i];
    if (tid < 40) sb[tid] = g_cbf[tid];
    __syncthreads();

    int f0 = tid << 4;
    int n, co, R0, C0, HW, pi0;
    bool big = (f0 < 2048);
    if (big) {
        n = f0 >> 10;
        int w_ = f0 & 1023;
        co = w_ >> 8;
        pi0 = (w_ >> 4) & 15;          // pj = 0..15
        R0 = 32 * n; C0 = 0; HW = 32;
    } else {
        int g = f0 - 2048;
        int n2 = g >> 8;
        n = n2 + 2;
        int w_ = g & 255;
        co = w_ >> 6;
        pi0 = (w_ >> 3) & 7;           // rows pi0, pi0+1; pj 0..7 each
        R0 = (16 * n2) & 63; C0 = 32 + 16 * (n2 >> 2); HW = 16;
    }

    float wreg[27];
    const float* wp = sw + (n * 4 + co) * 27;
#pragma unroll
    for (int t = 0; t < 27; t++) wreg[t] = wp[t];
    float bias = sb[n * 4 + co];

    float res[16];
    if (big) {
#pragma unroll
        for (int q = 0; q < 16; q++)
            res[q] = pool_feat(sx, R0, C0, HW, wreg, bias, pi0, q);
    } else {
#pragma unroll
        for (int q = 0; q < 8; q++)
            res[q] = pool_feat(sx, R0, C0, HW, wreg, bias, pi0, q);
#pragma unroll
        for (int q = 0; q < 8; q++)
            res[8 + q] = pool_feat(sx, R0, C0, HW, wreg, bias, pi0 + 1, q);
    }

    // split into bf16 hi/lo, pack, vectorized store
    uint32_t ph[8], pl[8];
#pragma unroll
    for (int u = 0; u < 8; u++) {
        __nv_bfloat16 h0 = __float2bfloat16(res[2 * u]);
        __nv_bfloat16 h1 = __float2bfloat16(res[2 * u + 1]);
        __nv_bfloat16 l0 = __float2bfloat16(res[2 * u]     - __bfloat162float(h0));
        __nv_bfloat16 l1 = __float2bfloat16(res[2 * u + 1] - __bfloat162float(h1));
        ph[u] = (uint32_t)__bfloat16_as_ushort(h0) | ((uint32_t)__bfloat16_as_ushort(h1) << 16);
        pl[u] = (uint32_t)__bfloat16_as_ushort(l0) | ((uint32_t)__bfloat16_as_ushort(l1) << 16);
    }
    size_t base = (size_t)b * FEAT_K + (size_t)tid * 16;
    uint4* oh = (uint4*)(g_featH + base);
    oh[0] = make_uint4(ph[0], ph[1], ph[2], ph[3]);
    oh[1] = make_uint4(ph[4], ph[5], ph[6], ph[7]);
    uint4* ol = (uint4*)(g_featL + base);
    ol[0] = make_uint4(pl[0], pl[1], pl[2], pl[3]);
    ol[1] = make_uint4(pl[4], pl[5], pl[6], pl[7]);
}

// =================================================================
// gemm (tensor cores): recv[m][j] = feat[m][:].W_fold[j][:] + noise[j]
// split-bf16: acc = AhiBhi + AhiBlo + AloBhi  (fp32-class accuracy)
// BM=64 BN=64 BK=32, 256 threads (8 warps, 2x4), mma.m16n8k16.
// grid (4096/64, 256/64) = (64, 4) = 256 CTAs.
// =================================================================
#define GP 40   // smem pitch in bf16 elements (conflict-free frag loads)

#define MMA_OP(d, a, b) asm volatile( \
    "mma.sync.aligned.m16n8k16.row.col.f32.bf16.bf16.f32 " \
    "{%0,%1,%2,%3},{%4,%5,%6,%7},{%8,%9},{%0,%1,%2,%3};" \
    : "+f"(d[0]), "+f"(d[1]), "+f"(d[2]), "+f"(d[3]) \
    : "r"(a[0]), "r"(a[1]), "r"(a[2]), "r"(a[3]), "r"(b[0]), "r"(b[1]))

__global__ void __launch_bounds__(256) gemm_bf16_kernel()
{
    __shared__ __nv_bfloat16 smAH[2][64 * GP];
    __shared__ __nv_bfloat16 smAL[2][64 * GP];
    __shared__ __nv_bfloat16 smBH[2][64 * GP];
    __shared__ __nv_bfloat16 smBL[2][64 * GP];

    int tid = threadIdx.x;
    int m0 = blockIdx.x * 64;
    int n0 = blockIdx.y * 64;
    int warp = tid >> 5, lane = tid & 31;
    int wm = (warp & 1) * 32;       // warp M offset
    int wn = (warp >> 1) * 16;      // warp N offset

    float acc[2][2][4];
#pragma unroll
    for (int i = 0; i < 2; i++)
#pragma unroll
        for (int j = 0; j < 2; j++)
#pragma unroll
            for (int c = 0; c < 4; c++) acc[i][j][c] = 0.f;

    // global->reg staging: each thread 2x uint2 (8 bf16) per matrix
    int lr = tid >> 3;              // 0..31
    int lc = (tid & 7) * 4;
    uint2 rAH[2], rAL[2], rBH[2], rBL[2];

#define GLOAD(K0) do { \
    size_t oa = (size_t)(m0 + lr) * FEAT_K + (K0) + lc; \
    size_t ob = (size_t)(n0 + lr) * FEAT_K + (K0) + lc; \
    rAH[0] = *(const uint2*)(g_featH + oa); \
    rAH[1] = *(const uint2*)(g_featH + oa + (size_t)32 * FEAT_K); \
    rAL[0] = *(const uint2*)(g_featL + oa); \
    rAL[1] = *(const uint2*)(g_featL + oa + (size_t)32 * FEAT_K); \
    rBH[0] = *(const uint2*)(g_WTH + ob); \
    rBH[1] = *(const uint2*)(g_WTH + ob + (size_t)32 * FEAT_K); \
    rBL[0] = *(const uint2*)(g_WTL + ob); \
    rBL[1] = *(const uint2*)(g_WTL + ob + (size_t)32 * FEAT_K); \
} while (0)

#define SSTORE(ST) do { \
    *(uint2*)(smAH[ST] + lr * GP + lc) = rAH[0]; \
    *(uint2*)(smAH[ST] + (lr + 32) * GP + lc) = rAH[1]; \
    *(uint2*)(smAL[ST] + lr * GP + lc) = rAL[0]; \
    *(uint2*)(smAL[ST] + (lr + 32) * GP + lc) = rAL[1]; \
    *(uint2*)(smBH[ST] + lr * GP + lc) = rBH[0]; \
    *(uint2*)(smBH[ST] + (lr + 32) * GP + lc) = rBH[1]; \
    *(uint2*)(smBL[ST] + lr * GP + lc) = rBL[0]; \
    *(uint2*)(smBL[ST] + (lr + 32) * GP + lc) = rBL[1]; \
} while (0)

    GLOAD(0);
    SSTORE(0);
    __syncthreads();

    int ar = wm + (lane >> 2);
    int lk = (lane & 3) * 2;

    for (int it = 0; it < FEAT_K / 32; ++it) {
        int st = it & 1;
        if (it < FEAT_K / 32 - 1) GLOAD((it + 1) * 32);  // overlap with mma

        const __nv_bfloat16* AH = smAH[st];
        const __nv_bfloat16* AL = smAL[st];
        const __nv_bfloat16* BH = smBH[st];
        const __nv_bfloat16* BL = smBL[st];

#pragma unroll
        for (int ks = 0; ks < 2; ks++) {
            int kk = ks * 16 + lk;
            uint32_t ah[2][4], al[2][4];
#pragma unroll
            for (int mf = 0; mf < 2; mf++) {
                int rb = ar + mf * 16;
                ah[mf][0] = *(const uint32_t*)(AH + rb * GP + kk);
                ah[mf][1] = *(const uint32_t*)(AH + (rb + 8) * GP + kk);
                ah[mf][2] = *(const uint32_t*)(AH + rb * GP + kk + 8);
                ah[mf][3] = *(const uint32_t*)(AH + (rb + 8) * GP + kk + 8);
                al[mf][0] = *(const uint32_t*)(AL + rb * GP + kk);
                al[mf][1] = *(const uint32_t*)(AL + (rb + 8) * GP + kk);
                al[mf][2] = *(const uint32_t*)(AL + rb * GP + kk + 8);
                al[mf][3] = *(const uint32_t*)(AL + (rb + 8) * GP + kk + 8);
            }
            uint32_t bh[2][2], bl[2][2];
#pragma unroll
            for (int nf = 0; nf < 2; nf++) {
                int nr = wn + nf * 8 + (lane >> 2);
                bh[nf][0] = *(const uint32_t*)(BH + nr * GP + kk);
                bh[nf][1] = *(const uint32_t*)(BH + nr * GP + kk + 8);
                bl[nf][0] = *(const uint32_t*)(BL + nr * GP + kk);
                bl[nf][1] = *(const uint32_t*)(BL + nr * GP + kk + 8);
            }
#pragma unroll
            for (int mf = 0; mf < 2; mf++)
#pragma unroll
                for (int nf = 0; nf < 2; nf++) {
                    MMA_OP(acc[mf][nf], ah[mf], bh[nf]);
                    MMA_OP(acc[mf][nf], ah[mf], bl[nf]);
                    MMA_OP(acc[mf][nf], al[mf], bh[nf]);
                }
        }
        if (it < FEAT_K / 32 - 1) {
            __syncthreads();
            SSTORE(st ^ 1);
            __syncthreads();
        }
    }

    // epilogue: add noise, write fp32 recv
    int gr = lane >> 2, gc2 = (lane & 3) * 2;
#pragma unroll
    for (int mf = 0; mf < 2; mf++)
#pragma unroll
        for (int nf = 0; nf < 2; nf++) {
            int col = n0 + wn + nf * 8 + gc2;
            float nzx = g_noise[col], nzy = g_noise[col + 1];
            int row0 = m0 + wm + mf * 16 + gr;
            float2 v0 = make_float2(acc[mf][nf][0] + nzx, acc[mf][nf][1] + nzy);
            float2 v1 = make_float2(acc[mf][nf][2] + nzx, acc[mf][nf][3] + nzy);
            *(float2*)(g_recv + (size_t)row0 * NCH + col) = v0;
            *(float2*)(g_recv + (size_t)(row0 + 8) * NCH + col) = v1;
        }
}

// =================================================================
// mlp: warp-per-sample. weights in smem with conflict-free pitch.
// grid(128) x 256 threads (8 warps), 4 samples per warp.
// =================================================================
#define W1P 257
#define W2P 129
#define W3P 65

__global__ void mlp_kernel(const float* __restrict__ fc1w, const float* __restrict__ fc1b,
                           const float* __restrict__ fc2w, const float* __restrict__ fc2b,
                           const float* __restrict__ outw, const float* __restrict__ outb,
                           float* __restrict__ out)
{
    extern __shared__ float sm[];
    float* W1 = sm;                     // 128 x 257
    float* W2 = W1 + 128 * W1P;         // 64 x 129
    float* W3 = W2 + 64 * W2P;          // 10 x 65
    float* B1 = W3 + 10 * W3P;          // 128
    float* B2 = B1 + 128;               // 64
    float* B3 = B2 + 64;                // 12
    float* scratch = B3 + 12;           // 8 warps * 448

    int tid = threadIdx.x;
    for (int t = tid; t < 128 * 256; t += 256) {
        int o = t >> 8, j = t & 255;
        W1[o * W1P + j] = fc1w[t];
    }
    for (int t = tid; t < 64 * 128; t += 256) {
        int o = t >> 7, j = t & 127;
        W2[o * W2P + j] = fc2w[t];
    }
    for (int t = tid; t < 640; t += 256) {
        int o = t >> 6, j = t & 63;
        W3[o * W3P + j] = outw[t];
    }
    if (tid < 128) B1[tid] = fc1b[tid];
    if (tid < 64)  B2[tid] = fc2b[tid];
    if (tid < 10)  B3[tid] = outb[tid];
    __syncthreads();

    int warp = tid >> 5, lane = tid & 31;
    float* rv = scratch + warp * 448;
    float* h2 = rv + 256;
    float* h3 = h2 + 128;

    for (int q = 0; q < 4; q++) {
        int s = (blockIdx.x * 8 + warp) * 4 + q;
#pragma unroll
        for (int u = 0; u < 8; u++)
            rv[lane + u * 32] = fmaxf(g_recv[(size_t)s * NCH + lane + u * 32], 0.f);
        __syncwarp();
#pragma unroll
        for (int u = 0; u < 4; u++) {
            int o = lane + u * 32;
            float acc = B1[o];
#pragma unroll 8
            for (int j = 0; j < 256; j++) acc += rv[j] * W1[o * W1P + j];
            h2[o] = fmaxf(acc, 0.f);
        }
        __syncwarp();
#pragma unroll
        for (int u = 0; u < 2; u++) {
            int o = lane + u * 32;
            float acc = B2[o];
#pragma unroll 8
            for (int j = 0; j < 128; j++) acc += h2[j] * W2[o * W2P + j];
            h3[o] = fmaxf(acc, 0.f);
        }
        __syncwarp();
        float logit = -INFINITY;
        if (lane < 10) {
            float acc = B3[lane];
#pragma unroll 8
            for (int j = 0; j < 64; j++) acc += h3[j] * W3[lane * W3P + j];
            logit = acc;
        }
        float m = logit;
#pragma unroll
        for (int off = 16; off; off >>= 1) m = fmaxf(m, __shfl_xor_sync(0xFFFFFFFFu, m, off));
        float e = (lane < 10) ? expf(logit - m) : 0.f;
        float ssum = e;
#pragma unroll
        for (int off = 16; off; off >>= 1) ssum += __shfl_xor_sync(0xFFFFFFFFu, ssum, off);
        if (lane < 10) out[s * 10 + lane] = logit - m - logf(ssum);
    }
}

// =================================================================
// launch
// =================================================================
extern "C" void kernel_launch(void* const* d_in, const int* in_sizes, int n_in,
                              void* d_out, int out_size)
{
    const float* x        = (const float*)d_in[0];
    const float* conv_w   = (const float*)d_in[1];
    const float* conv_b   = (const float*)d_in[2];
    const float* bn_gamma = (const float*)d_in[3];
    const float* bn_beta  = (const float*)d_in[4];
    const float* bn_mean  = (const float*)d_in[5];
    const float* bn_var   = (const float*)d_in[6];
    const float* cut_big  = (const float*)d_in[7];
    const float* cut_small= (const float*)d_in[8];
    const float* fc1_w    = (const float*)d_in[9];
    const float* fc1_b    = (const float*)d_in[10];
    const float* fc2_w    = (const float*)d_in[11];
    const float* fc2_b    = (const float*)d_in[12];
    const float* out_w    = (const float*)d_in[13];
    const float* out_b    = (const float*)d_in[14];
    const float* b_mat    = (const float*)d_in[15];
    const float* h_mat    = (const float*)d_in[16];
    const float* a_mat    = (const float*)d_in[17];
    const float* indicator= (const float*)d_in[18];
    const float* noise    = (const float*)d_in[19];
    float* out = (float*)d_out;

    cudaFuncSetAttribute(branch_kernel, cudaFuncAttributeMaxDynamicSharedMemorySize, 56 * 1024);
    cudaFuncSetAttribute(mlp_kernel, cudaFuncAttributeMaxDynamicSharedMemorySize, 186 * 1024);

    prep_s_kernel<<<10, 256>>>(b_mat, h_mat, a_mat, indicator, noise,
                               conv_w, conv_b, bn_gamma, bn_beta, bn_mean, bn_var);
    prep_w_kernel<<<2560, 256>>>(cut_big, cut_small);
    branch_kernel<<<4096, 256, 56 * 1024>>>(x);
    gemm_bf16_kernel<<<dim3(64, 4), 256>>>();
    mlp_kernel<<<128, 256, 186 * 1024>>>(fc1_w, fc1_b, fc2_w, fc2_b, out_w, out_b, out);
}

// round 3
// speedup vs baseline: 3.7844x; 3.0579x over previous
#include <cuda_runtime.h>
#include <cuda_bf16.h>
#include <math.h>
#include <stdint.h>

// ---------------- problem constants ----------------
#define B        4096
#define FEAT_K   4096     // 2*1024 + 8*256
#define NCH      256      // received channels
#define XSAMP    (3*64*64)

// ---------------- scratch (device globals; no allocs allowed) ----------------
__device__ __nv_bfloat16 g_featH[(size_t)B * FEAT_K];   // 32 MiB
__device__ __nv_bfloat16 g_featL[(size_t)B * FEAT_K];   // 32 MiB
__device__ __nv_bfloat16 g_WTH[(size_t)NCH * FEAT_K];   // 2 MiB, layout [j][k]
__device__ __nv_bfloat16 g_WTL[(size_t)NCH * FEAT_K];   // 2 MiB
__device__ float g_recv[(size_t)B * NCH];               // 4 MiB
__device__ float g_s[10 * 256];
__device__ float g_noise[256];
__device__ float g_cwf[10 * 4 * 27];                    // BN-folded conv weights
__device__ float g_cbf[10 * 4];                         // BN-folded conv bias

// =================================================================
// prep_s
// =================================================================
__global__ void prep_s_kernel(const float* __restrict__ b_mat,
                              const float* __restrict__ h_mat,
                              const float* __restrict__ a_mat,
                              const float* __restrict__ indicator,
                              const float* __restrict__ noise,
                              const float* __restrict__ conv_w,
                              const float* __restrict__ conv_b,
                              const float* __restrict__ gamma,
                              const float* __restrict__ beta,
                              const float* __restrict__ mean,
                              const float* __restrict__ var)
{
    int n = blockIdx.x;
    int j = threadIdx.x;   // 0..255

    float arow[5];
#pragma unroll
    for (int c = 0; c < 5; c++) {
        float s = 0.f;
#pragma unroll
        for (int m = 0; m < 5; m++) s += a_mat[(j * 5 + c) * 5 + m];
        arow[c] = s;
    }

    float hs[5] = {0.f, 0.f, 0.f, 0.f, 0.f};
    for (int k = 0; k < 64; k++) {
        float iv = indicator[j * 64 + k];
#pragma unroll
        for (int c = 0; c < 5; c++) hs[c] += iv * h_mat[(n * 64 + k) * 5 + c];
    }
    float hv = 0.f;
#pragma unroll
    for (int c = 0; c < 5; c++) hv += hs[c] * arow[c];

    g_s[n * 256 + j] = b_mat[n * 256 + j] * hv;

    if (n == 0) {
        float nt = 0.f;
#pragma unroll
        for (int c = 0; c < 5; c++) nt += noise[j * 5 + c] * arow[c];
        g_noise[j] = nt;
    }

    if (j < 108) {
        int co = j / 27, r = j % 27;
        int idx = n * 4 + co;
        float sc = gamma[idx] * rsqrtf(var[idx] + 1e-5f);
        g_cwf[idx * 27 + r] = conv_w[idx * 27 + r] * sc;
        if (r == 0)
            g_cbf[idx] = (conv_b[idx] - mean[idx]) * sc + beta[idx];
    }
}

// =================================================================
// prep_w: W_fold row-major [j][k], bf16 hi/lo.
// =================================================================
__global__ void prep_w_kernel(const float* __restrict__ cut_big,
                              const float* __restrict__ cut_small)
{
    int blk = blockIdx.x;
    int n = blk >> 8, j = blk & 255;
    float s = g_s[n * 256 + j];
    int tid = threadIdx.x;

    if (n < 2) {
        const float* src = cut_big + ((size_t)(n * 256 + j)) * 1024;
        size_t dst = (size_t)j * FEAT_K + n * 1024;
#pragma unroll
        for (int kk = tid; kk < 1024; kk += 256) {
            float v = src[kk] * s;
            __nv_bfloat16 h = __float2bfloat16(v);
            g_WTH[dst + kk] = h;
            g_WTL[dst + kk] = __float2bfloat16(v - __bfloat162float(h));
        }
    } else {
        int n2 = n - 2;
        const float* src = cut_small + ((size_t)(n2 * 256 + j)) * 256;
        size_t dst = (size_t)j * FEAT_K + 2048 + n2 * 256;
        float v = src[tid] * s;
        __nv_bfloat16 h = __float2bfloat16(v);
        g_WTH[dst + tid] = h;
        g_WTL[dst + tid] = __float2bfloat16(v - __bfloat162float(h));
    }
}

// =================================================================
// branch: one sample per block, smem image PITCH 65 (bank-conflict fix)
// =================================================================
#define SXP 65
#define SXC (64 * SXP)   // per-channel pitch

__device__ __forceinline__ float pool_feat(const float* __restrict__ sx,
                                           int R0, int C0, int HW,
                                           const float wreg[27], float bias,
                                           int pi, int pj)
{
    float t00 = bias, t01 = bias, t10 = bias, t11 = bias;
    int ib = 2 * pi - 1, jb = 2 * pj - 1;
    bool left = (jb >= 0);
    bool right = (jb + 3 < HW);
#pragma unroll
    for (int ci = 0; ci < 3; ci++) {
        const float* base = sx + ci * SXC + R0 * SXP + C0;
        float p[4][4];
#pragma unroll
        for (int u = 0; u < 4; u++) {
            int a = ib + u;
            bool va = (a >= 0) && (a < HW);
            const float* rp = base + a * SXP + jb;
            p[u][0] = (va && left)  ? rp[0] : 0.f;
            p[u][1] = va            ? rp[1] : 0.f;
            p[u][2] = va            ? rp[2] : 0.f;
            p[u][3] = (va && right) ? rp[3] : 0.f;
        }
#pragma unroll
        for (int di = 0; di < 3; di++)
#pragma unroll
            for (int dj = 0; dj < 3; dj++) {
                float wv = wreg[ci * 9 + di * 3 + dj];
                t00 += p[di    ][dj    ] * wv;
                t01 += p[di    ][dj + 1] * wv;
                t10 += p[di + 1][dj    ] * wv;
                t11 += p[di + 1][dj + 1] * wv;
            }
    }
    float mx = fmaxf(fmaxf(t00, t01), fmaxf(t10, t11));
    return fmaxf(mx, 0.f);
}

__global__ void __launch_bounds__(256) branch_kernel(const float* __restrict__ x)
{
    extern __shared__ float sm[];
    float* sx = sm;                 // [3][64][65]
    float* sw = sm + 3 * SXC;       // folded conv weights, 1080
    float* sb = sw + 1080;          // folded bias, 40

    int b = blockIdx.x;
    int tid = threadIdx.x;

    const float4* xin = (const float4*)(x + (size_t)b * XSAMP);
#pragma unroll 4
    for (int i = tid; i < 3 * 64 * 16; i += 256) {
        int r = i >> 4, q = i & 15;
        float4 v = xin[i];
        float* d = sx + r * SXP + q * 4;
        d[0] = v.x; d[1] = v.y; d[2] = v.z; d[3] = v.w;
    }
    for (int i = tid; i < 1080; i += 256) sw[i] = g_cwf[i];
    if (tid < 40) sb[tid] = g_cbf[tid];
    __syncthreads();

    int f0 = tid << 4;
    int n, co, R0, C0, HW, pi0;
    bool big = (f0 < 2048);
    if (big) {
        n = f0 >> 10;
        int w_ = f0 & 1023;
        co = w_ >> 8;
        pi0 = (w_ >> 4) & 15;          // pj = 0..15
        R0 = 32 * n; C0 = 0; HW = 32;
    } else {
        int g = f0 - 2048;
        int n2 = g >> 8;
        n = n2 + 2;
        int w_ = g & 255;
        co = w_ >> 6;
        pi0 = (w_ >> 3) & 7;           // rows pi0, pi0+1; pj 0..7 each
        R0 = (16 * n2) & 63; C0 = 32 + 16 * (n2 >> 2); HW = 16;
    }

    float wreg[27];
    const float* wp = sw + (n * 4 + co) * 27;
#pragma unroll
    for (int t = 0; t < 27; t++) wreg[t] = wp[t];
    float bias = sb[n * 4 + co];

    float res[16];
    if (big) {
#pragma unroll
        for (int q = 0; q < 16; q++)
            res[q] = pool_feat(sx, R0, C0, HW, wreg, bias, pi0, q);
    } else {
#pragma unroll
        for (int q = 0; q < 8; q++)
            res[q] = pool_feat(sx, R0, C0, HW, wreg, bias, pi0, q);
#pragma unroll
        for (int q = 0; q < 8; q++)
            res[8 + q] = pool_feat(sx, R0, C0, HW, wreg, bias, pi0 + 1, q);
    }

    uint32_t ph[8], pl[8];
#pragma unroll
    for (int u = 0; u < 8; u++) {
        __nv_bfloat16 h0 = __float2bfloat16(res[2 * u]);
        __nv_bfloat16 h1 = __float2bfloat16(res[2 * u + 1]);
        __nv_bfloat16 l0 = __float2bfloat16(res[2 * u]     - __bfloat162float(h0));
        __nv_bfloat16 l1 = __float2bfloat16(res[2 * u + 1] - __bfloat162float(h1));
        ph[u] = (uint32_t)__bfloat16_as_ushort(h0) | ((uint32_t)__bfloat16_as_ushort(h1) << 16);
        pl[u] = (uint32_t)__bfloat16_as_ushort(l0) | ((uint32_t)__bfloat16_as_ushort(l1) << 16);
    }
    size_t base = (size_t)b * FEAT_K + (size_t)tid * 16;
    uint4* oh = (uint4*)(g_featH + base);
    oh[0] = make_uint4(ph[0], ph[1], ph[2], ph[3]);
    oh[1] = make_uint4(ph[4], ph[5], ph[6], ph[7]);
    uint4* ol = (uint4*)(g_featL + base);
    ol[0] = make_uint4(pl[0], pl[1], pl[2], pl[3]);
    ol[1] = make_uint4(pl[4], pl[5], pl[6], pl[7]);
}

// =================================================================
// gemm (tensor cores, ldmatrix): recv = feat . W_fold^T + noise
// BM=64 BN=64 BK=64, 256 threads (8 warps 2x4), mma.m16n8k16 split-bf16.
// smem pitch 72 bf16 -> conflict-free ldmatrix & stores.
// =================================================================
#define GP3 72
#define STG_BF16 (4 * 64 * GP3)   // bf16 elems per stage (4 matrices)

#define MMA_OP(d, a, b) asm volatile( \
    "mma.sync.aligned.m16n8k16.row.col.f32.bf16.bf16.f32 " \
    "{%0,%1,%2,%3},{%4,%5,%6,%7},{%8,%9},{%0,%1,%2,%3};" \
    : "+f"(d[0]), "+f"(d[1]), "+f"(d[2]), "+f"(d[3]) \
    : "r"(a[0]), "r"(a[1]), "r"(a[2]), "r"(a[3]), "r"(b[0]), "r"(b[1]))

__device__ __forceinline__ void ldsm_x4(uint32_t* r, uint32_t addr) {
    asm volatile("ldmatrix.sync.aligned.m8n8.x4.shared.b16 {%0,%1,%2,%3}, [%4];"
        : "=r"(r[0]), "=r"(r[1]), "=r"(r[2]), "=r"(r[3]) : "r"(addr));
}
__device__ __forceinline__ void ldsm_x2(uint32_t* r, uint32_t addr) {
    asm volatile("ldmatrix.sync.aligned.m8n8.x2.shared.b16 {%0,%1}, [%2];"
        : "=r"(r[0]), "=r"(r[1]) : "r"(addr));
}

__global__ void __launch_bounds__(256) gemm_bf16_kernel()
{
    extern __shared__ __nv_bfloat16 gsm[];
    // per stage: AH, AL, BH, BL each 64*GP3 bf16
    int tid = threadIdx.x;
    int m0 = blockIdx.x * 64;
    int n0 = blockIdx.y * 64;
    int warp = tid >> 5, lane = tid & 31;
    int wm = (warp & 1) * 32;       // warp M offset
    int wn = (warp >> 1) * 16;      // warp N offset

    float acc[2][2][4];
#pragma unroll
    for (int i = 0; i < 2; i++)
#pragma unroll
        for (int j = 0; j < 2; j++)
#pragma unroll
            for (int c = 0; c < 4; c++) acc[i][j][c] = 0.f;

    // global->reg staging: 64x64 tile, each thread 2 consecutive uint4 per matrix
    int lr = tid >> 2;              // 0..63 (row)
    int lc = (tid & 3) * 16;        // bf16 col
    uint4 rAH[2], rAL[2], rBH[2], rBL[2];

#define GLOAD(K0) do { \
    size_t oa = (size_t)(m0 + lr) * FEAT_K + (K0) + lc; \
    size_t ob = (size_t)(n0 + lr) * FEAT_K + (K0) + lc; \
    rAH[0] = *(const uint4*)(g_featH + oa); \
    rAH[1] = *(const uint4*)(g_featH + oa + 8); \
    rAL[0] = *(const uint4*)(g_featL + oa); \
    rAL[1] = *(const uint4*)(g_featL + oa + 8); \
    rBH[0] = *(const uint4*)(g_WTH + ob); \
    rBH[1] = *(const uint4*)(g_WTH + ob + 8); \
    rBL[0] = *(const uint4*)(g_WTL + ob); \
    rBL[1] = *(const uint4*)(g_WTL + ob + 8); \
} while (0)

#define SSTORE(ST) do { \
    __nv_bfloat16* s_ = gsm + (ST) * STG_BF16; \
    *(uint4*)(s_ + lr * GP3 + lc) = rAH[0]; \
    *(uint4*)(s_ + lr * GP3 + lc + 8) = rAH[1]; \
    *(uint4*)(s_ + 64 * GP3 + lr * GP3 + lc) = rAL[0]; \
    *(uint4*)(s_ + 64 * GP3 + lr * GP3 + lc + 8) = rAL[1]; \
    *(uint4*)(s_ + 2 * 64 * GP3 + lr * GP3 + lc) = rBH[0]; \
    *(uint4*)(s_ + 2 * 64 * GP3 + lr * GP3 + lc + 8) = rBH[1]; \
    *(uint4*)(s_ + 3 * 64 * GP3 + lr * GP3 + lc) = rBL[0]; \
    *(uint4*)(s_ + 3 * 64 * GP3 + lr * GP3 + lc + 8) = rBL[1]; \
} while (0)

    GLOAD(0);
    SSTORE(0);
    __syncthreads();

    // ldmatrix lane geometry
    int t4  = lane >> 3;
    int ar4 = (lane & 7) + (t4 & 1) * 8;   // row within 16-row A frag
    int ac4 = (t4 >> 1) * 8;               // col offset 0/8
    int br2 = lane & 7;                    // row within 8-row B frag
    int bc2 = ((lane >> 3) & 1) * 8;       // col offset 0/8

    uint32_t sbase = (uint32_t)__cvta_generic_to_shared(gsm);

    for (int it = 0; it < FEAT_K / 64; ++it) {
        int st = it & 1;
        if (it < FEAT_K / 64 - 1) GLOAD((it + 1) * 64);

        uint32_t sAH = sbase + (uint32_t)(st * STG_BF16) * 2;
        uint32_t sAL = sAH + 64 * GP3 * 2;
        uint32_t sBH = sAL + 64 * GP3 * 2;
        uint32_t sBL = sBH + 64 * GP3 * 2;

#pragma unroll
        for (int ks = 0; ks < 4; ks++) {
            int kk = ks * 16;
            uint32_t ah[2][4], al[2][4], bh[2][2], bl[2][2];
#pragma unroll
            for (int mf = 0; mf < 2; mf++) {
                uint32_t ao = (uint32_t)((wm + mf * 16 + ar4) * GP3 + kk + ac4) * 2;
                ldsm_x4(ah[mf], sAH + ao);
                ldsm_x4(al[mf], sAL + ao);
            }
#pragma unroll
            for (int nf = 0; nf < 2; nf++) {
                uint32_t bo = (uint32_t)((wn + nf * 8 + br2) * GP3 + kk + bc2) * 2;
                ldsm_x2(bh[nf], sBH + bo);
                ldsm_x2(bl[nf], sBL + bo);
            }
#pragma unroll
            for (int mf = 0; mf < 2; mf++)
#pragma unroll
                for (int nf = 0; nf < 2; nf++) {
                    MMA_OP(acc[mf][nf], ah[mf], bh[nf]);
                    MMA_OP(acc[mf][nf], ah[mf], bl[nf]);
                    MMA_OP(acc[mf][nf], al[mf], bh[nf]);
                }
        }
        if (it < FEAT_K / 64 - 1) {
            __syncthreads();
            SSTORE(st ^ 1);
            __syncthreads();
        }
    }

    int gr = lane >> 2, gc2 = (lane & 3) * 2;
#pragma unroll
    for (int mf = 0; mf < 2; mf++)
#pragma unroll
        for (int nf = 0; nf < 2; nf++) {
            int col = n0 + wn + nf * 8 + gc2;
            float nzx = g_noise[col], nzy = g_noise[col + 1];
            int row0 = m0 + wm + mf * 16 + gr;
            float2 v0 = make_float2(acc[mf][nf][0] + nzx, acc[mf][nf][1] + nzy);
            float2 v1 = make_float2(acc[mf][nf][2] + nzx, acc[mf][nf][3] + nzy);
            *(float2*)(g_recv + (size_t)row0 * NCH + col) = v0;
            *(float2*)(g_recv + (size_t)(row0 + 8) * NCH + col) = v1;
        }
}

// =================================================================
// mlp: warp-per-sample; float4 inner loops, pitches multiple of 4.
// =================================================================
#define W1P 260
#define W2P 132
#define W3P 68

__global__ void mlp_kernel(const float* __restrict__ fc1w, const float* __restrict__ fc1b,
                           const float* __restrict__ fc2w, const float* __restrict__ fc2b,
                           const float* __restrict__ outw, const float* __restrict__ outb,
                           float* __restrict__ out)
{
    extern __shared__ float sm[];
    float* W1 = sm;                     // 128 x 260
    float* W2 = W1 + 128 * W1P;         // 64 x 132
    float* W3 = W2 + 64 * W2P;          // 10 x 68
    float* B1 = W3 + 10 * W3P;          // 128
    float* B2 = B1 + 128;               // 64
    float* B3 = B2 + 64;                // 12
    float* scratch = B3 + 12;           // 8 warps * 448

    int tid = threadIdx.x;
    for (int t = tid; t < 128 * 256; t += 256) {
        int o = t >> 8, j = t & 255;
        W1[o * W1P + j] = fc1w[t];
    }
    for (int t = tid; t < 64 * 128; t += 256) {
        int o = t >> 7, j = t & 127;
        W2[o * W2P + j] = fc2w[t];
    }
    for (int t = tid; t < 640; t += 256) {
        int o = t >> 6, j = t & 63;
        W3[o * W3P + j] = outw[t];
    }
    if (tid < 128) B1[tid] = fc1b[tid];
    if (tid < 64)  B2[tid] = fc2b[tid];
    if (tid < 10)  B3[tid] = outb[tid];
    __syncthreads();

    int warp = tid >> 5, lane = tid & 31;
    float* rv = scratch + warp * 448;
    float* h2 = rv + 256;
    float* h3 = h2 + 128;

    for (int q = 0; q < 4; q++) {
        int s = (blockIdx.x * 8 + warp) * 4 + q;
#pragma unroll
        for (int u = 0; u < 8; u++)
            rv[lane + u * 32] = fmaxf(g_recv[(size_t)s * NCH + lane + u * 32], 0.f);
        __syncwarp();
#pragma unroll
        for (int u = 0; u < 4; u++) {
            int o = lane + u * 32;
            const float* wrow = W1 + o * W1P;
            float acc = B1[o];
#pragma unroll 8
            for (int j4 = 0; j4 < 64; j4++) {
                float4 wv = *(const float4*)(wrow + j4 * 4);
                float4 rvv = *(const float4*)(rv + j4 * 4);
                acc += rvv.x * wv.x + rvv.y * wv.y + rvv.z * wv.z + rvv.w * wv.w;
            }
            h2[o] = fmaxf(acc, 0.f);
        }
        __syncwarp();
#pragma unroll
        for (int u = 0; u < 2; u++) {
            int o = lane + u * 32;
            const float* wrow = W2 + o * W2P;
            float acc = B2[o];
#pragma unroll 8
            for (int j4 = 0; j4 < 32; j4++) {
                float4 wv = *(const float4*)(wrow + j4 * 4);
                float4 hv = *(const float4*)(h2 + j4 * 4);
                acc += hv.x * wv.x + hv.y * wv.y + hv.z * wv.z + hv.w * wv.w;
            }
            h3[o] = fmaxf(acc, 0.f);
        }
        __syncwarp();
        float logit = -INFINITY;
        if (lane < 10) {
            const float* wrow = W3 + lane * W3P;
            float acc = B3[lane];
#pragma unroll
            for (int j4 = 0; j4 < 16; j4++) {
                float4 wv = *(const float4*)(wrow + j4 * 4);
                float4 hv = *(const float4*)(h3 + j4 * 4);
                acc += hv.x * wv.x + hv.y * wv.y + hv.z * wv.z + hv.w * wv.w;
            }
            logit = acc;
        }
        float m = logit;
#pragma unroll
        for (int off = 16; off; off >>= 1) m = fmaxf(m, __shfl_xor_sync(0xFFFFFFFFu, m, off));
        float e = (lane < 10) ? expf(logit - m) : 0.f;
        float ssum = e;
#pragma unroll
        for (int off = 16; off; off >>= 1) ssum += __shfl_xor_sync(0xFFFFFFFFu, ssum, off);
        if (lane < 10) out[s * 10 + lane] = logit - m - logf(ssum);
    }
}

// =================================================================
// launch
// =================================================================
extern "C" void kernel_launch(void* const* d_in, const int* in_sizes, int n_in,
                              void* d_out, int out_size)
{
    const float* x        = (const float*)d_in[0];
    const float* conv_w   = (const float*)d_in[1];
    const float* conv_b   = (const float*)d_in[2];
    const float* bn_gamma = (const float*)d_in[3];
    const float* bn_beta  = (const float*)d_in[4];
    const float* bn_mean  = (const float*)d_in[5];
    const float* bn_var   = (const float*)d_in[6];
    const float* cut_big  = (const float*)d_in[7];
    const float* cut_small= (const float*)d_in[8];
    const float* fc1_w    = (const float*)d_in[9];
    const float* fc1_b    = (const float*)d_in[10];
    const float* fc2_w    = (const float*)d_in[11];
    const float* fc2_b    = (const float*)d_in[12];
    const float* out_w    = (const float*)d_in[13];
    const float* out_b    = (const float*)d_in[14];
    const float* b_mat    = (const float*)d_in[15];
    const float* h_mat    = (const float*)d_in[16];
    const float* a_mat    = (const float*)d_in[17];
    const float* indicator= (const float*)d_in[18];
    const float* noise    = (const float*)d_in[19];
    float* out = (float*)d_out;

    int branch_smem = (3 * SXC + 1080 + 40) * 4;                  // ~54.5 KB
    int gemm_smem   = 2 * STG_BF16 * 2;                           // 73728 B
    int mlp_smem    = (128*W1P + 64*W2P + 10*W3P + 128 + 64 + 12 + 8*448) * 4;

    cudaFuncSetAttribute(branch_kernel, cudaFuncAttributeMaxDynamicSharedMemorySize, branch_smem);
    cudaFuncSetAttribute(gemm_bf16_kernel, cudaFuncAttributeMaxDynamicSharedMemorySize, gemm_smem);
    cudaFuncSetAttribute(mlp_kernel, cudaFuncAttributeMaxDynamicSharedMemorySize, mlp_smem);

    prep_s_kernel<<<10, 256>>>(b_mat, h_mat, a_mat, indicator, noise,
                               conv_w, conv_b, bn_gamma, bn_beta, bn_mean, bn_var);
    prep_w_kernel<<<2560, 256>>>(cut_big, cut_small);
    branch_kernel<<<4096, 256, branch_smem>>>(x);
    gemm_bf16_kernel<<<dim3(64, 4), 256, gemm_smem>>>();
    mlp_kernel<<<128, 256, mlp_smem>>>(fc1_w, fc1_b, fc2_w, fc2_b, out_w, out_b, out);
}